// round 14
// baseline (speedup 1.0000x reference)
#include <cuda_runtime.h>
#include <cuda_fp16.h>
#include <cstdint>
#include <cstddef>

// ============================================================================
// proj[b,c] = sum_{i,j} t[b,i] * W[c, i*512+j] * f[b,j]   (B=2048, F=512, C=64)
// out = relu(relu(proj + bp) @ W1^T + b1) @ W2^T + b2
//
// fp16 mma.sync.m16n8k16. R14: warp tile 64x32 via CHANNEL-split:
// 16 warps = (mw 2) x (nw 4) x (cp 2); warp cp handles channels {cp, cp+2}
// sequentially with a plain kc walk (R12's proven pattern). 187 B/mma ->
// L1TEX 192 cyc/step < tensor 256 cyc/step. Register-economical: single A
// fragment live at a time. Shell: G=4 channel-group CTA, A(128x512)+f
// resident, B direct-LDG ping-pong, staged prologue, no mainloop syncs.
// ============================================================================

// g_T [bt256(8)][kc16(32)][mt(16)][lane(32)][4 u32]     (2 MB)
// g_W [c(64)][jt(4)][kc16(32)][nt(16)][lane(32)][2 u32] (33.5 MB)
__device__ uint32_t g_T[8 * 32 * 16 * 32 * 4];
__device__ uint32_t g_W[64 * 4 * 32 * 16 * 32 * 2];
__device__ float    g_partial[16 * 2048 * 64];

// ---------------- helpers ----------------
__device__ __forceinline__ uint32_t packh2(float lo, float hi) {
    __half2 h = __floats2half2_rn(lo, hi);
    return *(uint32_t*)&h;
}
__device__ __forceinline__ void cp16(uint32_t dst_smem, const void* src) {
    asm volatile("cp.async.cg.shared.global [%0], [%1], 16;" :: "r"(dst_smem), "l"(src));
}
__device__ __forceinline__ void cp_commit() {
    asm volatile("cp.async.commit_group;" ::: "memory");
}
__device__ __forceinline__ void mma_f16(float* d, const uint32_t* a, const uint32_t* b) {
    asm volatile(
        "mma.sync.aligned.m16n8k16.row.col.f32.f16.f16.f32 "
        "{%0,%1,%2,%3},{%4,%5,%6,%7},{%8,%9},{%0,%1,%2,%3};"
        : "+f"(d[0]), "+f"(d[1]), "+f"(d[2]), "+f"(d[3])
        : "r"(a[0]), "r"(a[1]), "r"(a[2]), "r"(a[3]), "r"(b[0]), "r"(b[1]));
}

// ---------------- conv (unchanged: fragment-order fp16) ----------------
__global__ void conv_kernel(const float* __restrict__ t, const float* __restrict__ W) {
    if (blockIdx.x < 2048) {
        __shared__ float ws[64 * 132];
        int b = blockIdx.x;
        int c = b >> 5, jt = (b >> 3) & 3, ktile = b & 7;
        int tid = threadIdx.x, lane = tid & 31, warp = tid >> 5;

        const float* src = W + (size_t)c * 262144 + (size_t)(ktile * 64) * 512 + jt * 128;
#pragma unroll
        for (int r = 0; r < 8; r++) {
            int k = r * 8 + warp;
            float4 v = *(const float4*)&src[(size_t)k * 512 + lane * 4];
            float* d = &ws[k * 132 + lane * 4];
            d[0] = v.x; d[1] = v.y; d[2] = v.z; d[3] = v.w;
        }
        __syncthreads();

#pragma unroll
        for (int i = 0; i < 8; i++) {
            int p = warp * 8 + i;
            int q = p >> 4, nt = p & 15;
            int k0 = q * 16 + (lane & 3) * 2;
            int n  = nt * 8 + (lane >> 2);
            uint32_t v0 = packh2(ws[k0 * 132 + n],       ws[(k0 + 1) * 132 + n]);
            uint32_t v1 = packh2(ws[(k0 + 8) * 132 + n], ws[(k0 + 9) * 132 + n]);
            size_t base = ((size_t)((c * 4 + jt) * 32 + ktile * 4 + q) * 16 + nt) * 64 + lane * 2;
            *(uint2*)&g_W[base] = make_uint2(v0, v1);
        }
    } else {
        int gid = (blockIdx.x - 2048) * 256 + threadIdx.x;
        int lane  = gid & 31;
        int mt    = (gid >> 5) & 15;
        int kc    = (gid >> 9) & 31;
        int btile = gid >> 14;
        int row = btile * 256 + mt * 16 + (lane >> 2);
        int k0  = kc * 16 + (lane & 3) * 2;
        float2 p00 = *(const float2*)&t[(size_t)row * 512 + k0];
        float2 p10 = *(const float2*)&t[(size_t)(row + 8) * 512 + k0];
        float2 p01 = *(const float2*)&t[(size_t)row * 512 + k0 + 8];
        float2 p11 = *(const float2*)&t[(size_t)(row + 8) * 512 + k0 + 8];
        *(uint4*)&g_T[(size_t)gid * 4] =
            make_uint4(packh2(p00.x, p00.y), packh2(p10.x, p10.y),
                       packh2(p01.x, p01.y), packh2(p11.x, p11.y));
    }
}

// ---------------- GEMM + f-dot epilogue ----------------
// CTA: 128(m) x 128(n) x G=4 channels, 512 threads / 16 warps.
// warp = (cp<<3) | (nw<<1) | mw: mw in {0,1} (64 rows), nw in {0..3} (32 cols),
// cp in {0,1}: this warp handles channels {c0+cp, c0+cp+2} sequentially.
// Warp tile 64x32, acc[4][4][4] = 64 regs, single A fragment live.
static constexpr int G = 4;
static constexpr uint32_t SMEM_A  = 131072;
static constexpr uint32_t SMEM_F  = 128 * 132 * 4;       // 67584
static constexpr uint32_t SMEM_GEMM = SMEM_A + SMEM_F;   // 198656

__global__ __launch_bounds__(512, 1) void gemm_kernel(const float* __restrict__ f_feat) {
    extern __shared__ __align__(16) unsigned char smem_dyn[];
    uint32_t* smem = (uint32_t*)smem_dyn;
    int tid = threadIdx.x;
    int lane = tid & 31, warp = tid >> 5;
    int mw = warp & 1, nw = (warp >> 1) & 3, cp = warp >> 3;
    int btile = blockIdx.x, jt = blockIdx.y, c0 = blockIdx.z * G;

    const char* gA = (const char*)g_T + (size_t)(btile >> 1) * 32 * 8192 + (btile & 1) * 4096;
    uint32_t sbase = (uint32_t)__cvta_generic_to_shared(smem);

    // --- prologue: A in 4 cp.async groups (8 slabs each), then f as group 5 ---
    int half = tid >> 8;
    int toff = (tid & 255) * 16;
#pragma unroll
    for (int g = 0; g < 4; g++) {
#pragma unroll
        for (int i = 0; i < 4; i++) {
            int slab = g * 8 + i * 2 + half;
            cp16(sbase + slab * 4096 + toff, gA + (size_t)slab * 8192 + toff);
        }
        cp_commit();
    }
    const float* fsrc = f_feat + (size_t)(btile * 128) * 512 + jt * 128;
#pragma unroll
    for (int k = 0; k < 8; k++) {
        int i = k * 512 + tid;
        int row = i >> 5, cg = i & 31;
        cp16(sbase + SMEM_A + row * 528 + cg * 16, fsrc + (size_t)row * 512 + cg * 4);
    }
    cp_commit();

    float acc[4][4][4];
#pragma unroll
    for (int mt = 0; mt < 4; mt++)
#pragma unroll
        for (int nt = 0; nt < 4; nt++)
#pragma unroll
            for (int q = 0; q < 4; q++) acc[mt][nt][q] = 0.f;

    // B stream: channel ch0 = c0+cp now, ch1 = c0+cp+2 after. Ping-pong regs.
    const uint2* __restrict__ gB = (const uint2*)g_W;
    const size_t Boff = (size_t)(nw * 4) * 32 + lane;    // + (c*4+jt)*32*512 + kc*512
    size_t Bc0 = ((size_t)((c0 + cp) * 4 + jt) * 32) * 512 + Boff;
    size_t Bc1 = Bc0 + (size_t)2 * 4 * 32 * 512;         // channel +2
    uint2 breg[2][4];
#pragma unroll
    for (int nt = 0; nt < 4; nt++) breg[0][nt] = gB[Bc0 + nt * 32];

    const uint32_t* sA = smem;
    float* fs = (float*)(smem_dyn + SMEM_A);

#pragma unroll 1
    for (int ic = 0; ic < 2; ic++) {
        size_t Bcur = ic ? Bc1 : Bc0;
#pragma unroll 1
        for (int kc = 0; kc < 32; kc++) {
            if (ic == 0 && (kc & 7) == 0) {
                switch (kc >> 3) {
                    case 0: asm volatile("cp.async.wait_group 4;" ::: "memory"); break;
                    case 1: asm volatile("cp.async.wait_group 3;" ::: "memory"); break;
                    case 2: asm volatile("cp.async.wait_group 2;" ::: "memory"); break;
                    default: asm volatile("cp.async.wait_group 1;" ::: "memory"); break;
                }
                __syncthreads();
            }
            int s = ic * 32 + kc;
            // prefetch next step's B
            if (s + 1 < 64) {
                size_t bi = (kc + 1 < 32) ? (Bcur + (size_t)(kc + 1) * 512)
                                          : Bc1;
#pragma unroll
                for (int nt = 0; nt < 4; nt++)
                    breg[(s + 1) & 1][nt] = gB[bi + nt * 32];
            }
            const uint32_t* pA = sA + (size_t)kc * 1024;
            const uint2* bu = breg[s & 1];
#pragma unroll
            for (int mt = 0; mt < 4; mt++) {
                uint4 aa = *(const uint4*)&pA[((mw * 4 + mt) * 32 + lane) * 4];
                uint32_t afr[4] = {aa.x, aa.y, aa.z, aa.w};
#pragma unroll
                for (int nt = 0; nt < 4; nt++)
                    mma_f16(acc[mt][nt], afr, (const uint32_t*)&bu[nt]);
            }
        }

        // ---- epilogue for channel c0 + cp + 2*ic ----
        if (ic == 0) {
            asm volatile("cp.async.wait_group 0;" ::: "memory");
            __syncthreads();
        }
        int c = c0 + cp + 2 * ic;
        int slice = jt * 4 + nw;
#pragma unroll
        for (int mt = 0; mt < 4; mt++) {
#pragma unroll
            for (int h = 0; h < 2; h++) {
                int fl = mw * 64 + mt * 16 + (lane >> 2) + 8 * h;   // local row 0..127
                float sum = 0.f;
#pragma unroll
                for (int nt = 0; nt < 4; nt++) {
                    float2 fv = *(const float2*)&fs[fl * 132 + nw * 32 + nt * 8 + 2 * (lane & 3)];
                    sum = fmaf(acc[mt][nt][h * 2], fv.x, sum);
                    sum = fmaf(acc[mt][nt][h * 2 + 1], fv.y, sum);
                }
                sum += __shfl_xor_sync(0xffffffffu, sum, 1);
                sum += __shfl_xor_sync(0xffffffffu, sum, 2);
                if ((lane & 3) == 0) {
                    int bb = btile * 128 + fl;
                    g_partial[(size_t)slice * 131072 + (size_t)bb * 64 + c] = sum;
                }
            }
        }
#pragma unroll
        for (int mt = 0; mt < 4; mt++)
#pragma unroll
            for (int nt = 0; nt < 4; nt++)
#pragma unroll
                for (int q = 0; q < 4; q++) acc[mt][nt][q] = 0.f;
    }
}

// ---------------- MLP: sum 16 slices + bias + relu + 64->32->1 ----------------
__global__ void mlp_kernel(const float* __restrict__ b_proj, const float* __restrict__ W1,
                           const float* __restrict__ b1, const float* __restrict__ W2,
                           const float* __restrict__ b2, float* __restrict__ out) {
    __shared__ float sW1[2048], sb1[32], sW2[32], sbp[64];
    int tid = threadIdx.x;
    for (int i = tid; i < 2048; i += 32) sW1[i] = W1[i];
    if (tid < 32) { sb1[tid] = b1[tid]; sW2[tid] = W2[tid]; }
    for (int i = tid; i < 64; i += 32) sbp[i] = b_proj[i];
    __syncthreads();

    int b = blockIdx.x * 32 + tid;
    float h[64];
#pragma unroll
    for (int cg = 0; cg < 16; cg++) {
        float4 v = *(const float4*)&g_partial[(size_t)b * 64 + cg * 4];
#pragma unroll
        for (int s = 1; s < 16; s++) {
            float4 p = *(const float4*)&g_partial[(size_t)s * 131072 + (size_t)b * 64 + cg * 4];
            v.x += p.x; v.y += p.y; v.z += p.z; v.w += p.w;
        }
        h[cg * 4 + 0] = fmaxf(v.x + sbp[cg * 4 + 0], 0.f);
        h[cg * 4 + 1] = fmaxf(v.y + sbp[cg * 4 + 1], 0.f);
        h[cg * 4 + 2] = fmaxf(v.z + sbp[cg * 4 + 2], 0.f);
        h[cg * 4 + 3] = fmaxf(v.w + sbp[cg * 4 + 3], 0.f);
    }
    float logit = b2[0];
#pragma unroll
    for (int k = 0; k < 32; k++) {
        float a = sb1[k];
#pragma unroll
        for (int cc = 0; cc < 64; cc++)
            a = fmaf(h[cc], sW1[k * 64 + cc], a);
        logit = fmaf(fmaxf(a, 0.f), sW2[k], logit);
    }
    out[b] = logit;
}

// ---------------- launcher ----------------
extern "C" void kernel_launch(void* const* d_in, const int* in_sizes, int n_in,
                              void* d_out, int out_size) {
    const float* t_feat = (const float*)d_in[0];
    const float* f_feat = (const float*)d_in[1];
    const float* W_proj = (const float*)d_in[2];
    const float* b_proj = (const float*)d_in[3];
    const float* W1     = (const float*)d_in[4];
    const float* b1     = (const float*)d_in[5];
    const float* W2     = (const float*)d_in[6];
    const float* b2     = (const float*)d_in[7];
    float* out = (float*)d_out;

    cudaFuncSetAttribute(gemm_kernel, cudaFuncAttributeMaxDynamicSharedMemorySize, SMEM_GEMM);

    conv_kernel<<<2560, 256>>>(t_feat, W_proj);
    dim3 grid(16, 4, 16);   // (btile, jt, c-group) = 1024 CTAs
    gemm_kernel<<<grid, 512, SMEM_GEMM>>>(f_feat);
    mlp_kernel<<<64, 32>>>(b_proj, W1, b1, W2, b2, out);
}

// round 15
// speedup vs baseline: 1.5311x; 1.5311x over previous
#include <cuda_runtime.h>
#include <cuda_fp16.h>
#include <cstdint>
#include <cstddef>

// ============================================================================
// proj[b,c] = sum_{i,j} t[b,i] * W[c, i*512+j] * f[b,j]   (B=2048, F=512, C=64)
// out = relu(relu(proj + bp) @ W1^T + b1) @ W2^T + b2
//
// fp16 mma.sync.m16n8k16. R15: 64x32 warp tiles at 256thr/2CTAs-per-SM via
// K-split across CTAs. CTA = (btile128, jt128, kh in {0,1}, cgroup of 4).
// A K-half (64KB) + f tile (fp16, 34KB) resident in smem; B direct-LDG with
// STATIC ring-2 prefetch (distance 2, compile-time parity -> no spills).
// 32 deterministic partial slices; mlp sums them.
// ============================================================================

// g_T [bt256(8)][kc16(32)][mt(16)][lane(32)][4 u32]     (2 MB)
// g_W [c(64)][jt(4)][kc16(32)][nt(16)][lane(32)][2 u32] (33.5 MB)
__device__ uint32_t g_T[8 * 32 * 16 * 32 * 4];
__device__ uint32_t g_W[64 * 4 * 32 * 16 * 32 * 2];
__device__ __half   g_F[2048 * 512];                     // f in fp16 (2 MB)
__device__ float    g_partial[32 * 2048 * 64];           // 16 MB

// ---------------- helpers ----------------
__device__ __forceinline__ uint32_t packh2(float lo, float hi) {
    __half2 h = __floats2half2_rn(lo, hi);
    return *(uint32_t*)&h;
}
__device__ __forceinline__ void cp16(uint32_t dst_smem, const void* src) {
    asm volatile("cp.async.cg.shared.global [%0], [%1], 16;" :: "r"(dst_smem), "l"(src));
}
__device__ __forceinline__ void cp_commit() {
    asm volatile("cp.async.commit_group;" ::: "memory");
}
__device__ __forceinline__ void mma_f16(float* d, const uint32_t* a, const uint32_t* b) {
    asm volatile(
        "mma.sync.aligned.m16n8k16.row.col.f32.f16.f16.f32 "
        "{%0,%1,%2,%3},{%4,%5,%6,%7},{%8,%9},{%0,%1,%2,%3};"
        : "+f"(d[0]), "+f"(d[1]), "+f"(d[2]), "+f"(d[3])
        : "r"(a[0]), "r"(a[1]), "r"(a[2]), "r"(a[3]), "r"(b[0]), "r"(b[1]));
}

// ---------------- conv: W, t -> mma-fragment fp16; f -> plain fp16 ----------------
__global__ void conv_kernel(const float* __restrict__ t, const float* __restrict__ W,
                            const float* __restrict__ f) {
    if (blockIdx.x < 2048) {
        __shared__ float ws[64 * 132];
        int b = blockIdx.x;
        int c = b >> 5, jt = (b >> 3) & 3, ktile = b & 7;
        int tid = threadIdx.x, lane = tid & 31, warp = tid >> 5;

        const float* src = W + (size_t)c * 262144 + (size_t)(ktile * 64) * 512 + jt * 128;
#pragma unroll
        for (int r = 0; r < 8; r++) {
            int k = r * 8 + warp;
            float4 v = *(const float4*)&src[(size_t)k * 512 + lane * 4];
            float* d = &ws[k * 132 + lane * 4];
            d[0] = v.x; d[1] = v.y; d[2] = v.z; d[3] = v.w;
        }
        __syncthreads();

#pragma unroll
        for (int i = 0; i < 8; i++) {
            int p = warp * 8 + i;
            int q = p >> 4, nt = p & 15;
            int k0 = q * 16 + (lane & 3) * 2;
            int n  = nt * 8 + (lane >> 2);
            uint32_t v0 = packh2(ws[k0 * 132 + n],       ws[(k0 + 1) * 132 + n]);
            uint32_t v1 = packh2(ws[(k0 + 8) * 132 + n], ws[(k0 + 9) * 132 + n]);
            size_t base = ((size_t)((c * 4 + jt) * 32 + ktile * 4 + q) * 16 + nt) * 64 + lane * 2;
            *(uint2*)&g_W[base] = make_uint2(v0, v1);
        }
    } else if (blockIdx.x < 2560) {
        int gid = (blockIdx.x - 2048) * 256 + threadIdx.x;
        int lane  = gid & 31;
        int mt    = (gid >> 5) & 15;
        int kc    = (gid >> 9) & 31;
        int btile = gid >> 14;
        int row = btile * 256 + mt * 16 + (lane >> 2);
        int k0  = kc * 16 + (lane & 3) * 2;
        float2 p00 = *(const float2*)&t[(size_t)row * 512 + k0];
        float2 p10 = *(const float2*)&t[(size_t)(row + 8) * 512 + k0];
        float2 p01 = *(const float2*)&t[(size_t)row * 512 + k0 + 8];
        float2 p11 = *(const float2*)&t[(size_t)(row + 8) * 512 + k0 + 8];
        *(uint4*)&g_T[(size_t)gid * 4] =
            make_uint4(packh2(p00.x, p00.y), packh2(p10.x, p10.y),
                       packh2(p01.x, p01.y), packh2(p11.x, p11.y));
    } else {
        // convF: fp32 -> fp16, 8 elements per thread
        int gid = (blockIdx.x - 2560) * 256 + threadIdx.x;   // [0, 131072)
        size_t i8 = (size_t)gid * 8;
        float4 a = *(const float4*)&f[i8];
        float4 b = *(const float4*)&f[i8 + 4];
        uint4 o = make_uint4(packh2(a.x, a.y), packh2(a.z, a.w),
                             packh2(b.x, b.y), packh2(b.z, b.w));
        *(uint4*)&g_F[i8] = o;
    }
}

// ---------------- GEMM + f-dot epilogue ----------------
// CTA: 128(m) x 128(n) x K-half(256) x 4 channels. 256 thr / 8 warps:
// mw = warp&1 (64 rows), nw = warp>>1 (32 cols). acc[4][4][4] = 64 regs.
// smem: A 16 slabs x 4KB = 64KB at [0, 65536); f fp16 128 x 136 halfs at
// [65536, +34816). Total 100352 B/CTA, 2 CTAs/SM.
static constexpr uint32_t SMEM_AOFF = 65536;
static constexpr uint32_t SMEM_GEMM = 65536 + 128 * 136 * 2;   // 100352

__global__ __launch_bounds__(256, 2) void gemm_kernel() {
    extern __shared__ __align__(16) unsigned char smem_dyn[];
    uint32_t* smem = (uint32_t*)smem_dyn;
    int tid = threadIdx.x;
    int lane = tid & 31, warp = tid >> 5;
    int mw = warp & 1, nw = warp >> 1;
    int btile = blockIdx.x, jt = blockIdx.y;
    int cg = blockIdx.z & 15, kh = blockIdx.z >> 4;
    int c0 = cg * 4;

    const char* gA = (const char*)g_T + (size_t)(btile >> 1) * 262144
                   + (btile & 1) * 4096 + (size_t)kh * 16 * 8192;
    uint32_t sbase = (uint32_t)__cvta_generic_to_shared(smem);

    // --- prologue: A 16 slabs in 4 cp.async groups, then f (fp16) as group 5 ---
#pragma unroll
    for (int g = 0; g < 4; g++) {
#pragma unroll
        for (int i = 0; i < 4; i++) {
            int slab = g * 4 + i;
            cp16(sbase + slab * 4096 + tid * 16, gA + (size_t)slab * 8192 + tid * 16);
        }
        cp_commit();
    }
#pragma unroll
    for (int r = 0; r < 8; r++) {
        int i = r * 256 + tid;              // [0, 2048)
        int row = i >> 4, c16 = i & 15;
        const __half* fsrc = g_F + ((size_t)(btile * 128 + row) * 512 + jt * 128 + c16 * 8);
        cp16(sbase + SMEM_AOFF + row * 272 + c16 * 16, fsrc);
    }
    cp_commit();

    float acc[4][4][4];
#pragma unroll
    for (int mt = 0; mt < 4; mt++)
#pragma unroll
        for (int nt = 0; nt < 4; nt++)
#pragma unroll
            for (int q = 0; q < 4; q++) acc[mt][nt][q] = 0.f;

    // B stream. uint2 index: ((c*4+jt)*32 + kh*16 + kc)*512 + (nw*4+nt)*32 + lane
    const uint2* __restrict__ gB = (const uint2*)g_W;
    const size_t Bbase = ((size_t)(c0 * 4 + jt) * 32 + kh * 16) * 512 + nw * 128 + lane;
    uint2 bA[4], bB[4];
#pragma unroll
    for (int nt = 0; nt < 4; nt++) bA[nt] = gB[Bbase + nt * 32];
#pragma unroll
    for (int nt = 0; nt < 4; nt++) bB[nt] = gB[Bbase + 512 + nt * 32];

    const uint32_t* sA = smem;
    const __half2* fs = (const __half2*)(smem_dyn + SMEM_AOFF);

#pragma unroll 1
    for (int ci = 0; ci < 4; ci++) {
        size_t Bcur = Bbase + (size_t)ci * 65536;
        size_t Bnext = (ci < 3) ? Bcur + 65536 : Bcur;   // ci==3: harmless reload
#pragma unroll
        for (int kc2 = 0; kc2 < 8; kc2++) {
            const int kcA = kc2 * 2, kcB = kc2 * 2 + 1;
            if (ci == 0 && (kcA & 3) == 0) {
                switch (kcA >> 2) {
                    case 0: asm volatile("cp.async.wait_group 4;" ::: "memory"); break;
                    case 1: asm volatile("cp.async.wait_group 3;" ::: "memory"); break;
                    case 2: asm volatile("cp.async.wait_group 2;" ::: "memory"); break;
                    default: asm volatile("cp.async.wait_group 1;" ::: "memory"); break;
                }
                __syncthreads();
            }
            // ---- step kcA: use bA, then reload bA for step kcA+2 ----
            {
                const uint32_t* pA = sA + (size_t)kcA * 1024;
#pragma unroll
                for (int mt = 0; mt < 4; mt++) {
                    uint4 aa = *(const uint4*)&pA[((mw * 4 + mt) * 32 + lane) * 4];
                    uint32_t afr[4] = {aa.x, aa.y, aa.z, aa.w};
#pragma unroll
                    for (int nt = 0; nt < 4; nt++)
                        mma_f16(acc[mt][nt], afr, (const uint32_t*)&bA[nt]);
                }
                size_t pi = (kcA + 2 < 16) ? Bcur + (size_t)(kcA + 2) * 512
                                           : Bnext + (size_t)(kcA - 14) * 512;
#pragma unroll
                for (int nt = 0; nt < 4; nt++) bA[nt] = gB[pi + nt * 32];
            }
            // ---- step kcB: use bB, then reload bB for step kcB+2 ----
            {
                const uint32_t* pA = sA + (size_t)kcB * 1024;
#pragma unroll
                for (int mt = 0; mt < 4; mt++) {
                    uint4 aa = *(const uint4*)&pA[((mw * 4 + mt) * 32 + lane) * 4];
                    uint32_t afr[4] = {aa.x, aa.y, aa.z, aa.w};
#pragma unroll
                    for (int nt = 0; nt < 4; nt++)
                        mma_f16(acc[mt][nt], afr, (const uint32_t*)&bB[nt]);
                }
                size_t pi = (kcB + 2 < 16) ? Bcur + (size_t)(kcB + 2) * 512
                                           : Bnext + (size_t)(kcB - 14) * 512;
#pragma unroll
                for (int nt = 0; nt < 4; nt++) bB[nt] = gB[pi + nt * 32];
            }
        }

        // ---- epilogue for channel c0+ci ----
        if (ci == 0) {
            asm volatile("cp.async.wait_group 0;" ::: "memory");
            __syncthreads();
        }
        int c = c0 + ci;
        int slice = (jt * 4 + nw) * 2 + kh;
#pragma unroll
        for (int mt = 0; mt < 4; mt++) {
#pragma unroll
            for (int h = 0; h < 2; h++) {
                int fl = mw * 64 + mt * 16 + (lane >> 2) + 8 * h;   // local row 0..127
                float sum = 0.f;
#pragma unroll
                for (int nt = 0; nt < 4; nt++) {
                    __half2 hv = fs[fl * 68 + nw * 16 + nt * 4 + (lane & 3)];
                    float2 fv = __half22float2(hv);
                    sum = fmaf(acc[mt][nt][h * 2], fv.x, sum);
                    sum = fmaf(acc[mt][nt][h * 2 + 1], fv.y, sum);
                }
                sum += __shfl_xor_sync(0xffffffffu, sum, 1);
                sum += __shfl_xor_sync(0xffffffffu, sum, 2);
                if ((lane & 3) == 0) {
                    int bb = btile * 128 + fl;
                    g_partial[(size_t)slice * 131072 + (size_t)bb * 64 + c] = sum;
                }
            }
        }
#pragma unroll
        for (int mt = 0; mt < 4; mt++)
#pragma unroll
            for (int nt = 0; nt < 4; nt++)
#pragma unroll
                for (int q = 0; q < 4; q++) acc[mt][nt][q] = 0.f;
    }
}

// ---------------- MLP: sum 32 slices + bias + relu + 64->32->1 ----------------
__global__ void mlp_kernel(const float* __restrict__ b_proj, const float* __restrict__ W1,
                           const float* __restrict__ b1, const float* __restrict__ W2,
                           const float* __restrict__ b2, float* __restrict__ out) {
    __shared__ float sW1[2048], sb1[32], sW2[32], sbp[64];
    int tid = threadIdx.x;
    for (int i = tid; i < 2048; i += 32) sW1[i] = W1[i];
    if (tid < 32) { sb1[tid] = b1[tid]; sW2[tid] = W2[tid]; }
    for (int i = tid; i < 64; i += 32) sbp[i] = b_proj[i];
    __syncthreads();

    int b = blockIdx.x * 32 + tid;
    float h[64];
#pragma unroll
    for (int cg = 0; cg < 16; cg++) {
        float4 v = *(const float4*)&g_partial[(size_t)b * 64 + cg * 4];
#pragma unroll
        for (int s = 1; s < 32; s++) {
            float4 p = *(const float4*)&g_partial[(size_t)s * 131072 + (size_t)b * 64 + cg * 4];
            v.x += p.x; v.y += p.y; v.z += p.z; v.w += p.w;
        }
        h[cg * 4 + 0] = fmaxf(v.x + sbp[cg * 4 + 0], 0.f);
        h[cg * 4 + 1] = fmaxf(v.y + sbp[cg * 4 + 1], 0.f);
        h[cg * 4 + 2] = fmaxf(v.z + sbp[cg * 4 + 2], 0.f);
        h[cg * 4 + 3] = fmaxf(v.w + sbp[cg * 4 + 3], 0.f);
    }
    float logit = b2[0];
#pragma unroll
    for (int k = 0; k < 32; k++) {
        float a = sb1[k];
#pragma unroll
        for (int cc = 0; cc < 64; cc++)
            a = fmaf(h[cc], sW1[k * 64 + cc], a);
        logit = fmaf(fmaxf(a, 0.f), sW2[k], logit);
    }
    out[b] = logit;
}

// ---------------- launcher ----------------
extern "C" void kernel_launch(void* const* d_in, const int* in_sizes, int n_in,
                              void* d_out, int out_size) {
    const float* t_feat = (const float*)d_in[0];
    const float* f_feat = (const float*)d_in[1];
    const float* W_proj = (const float*)d_in[2];
    const float* b_proj = (const float*)d_in[3];
    const float* W1     = (const float*)d_in[4];
    const float* b1     = (const float*)d_in[5];
    const float* W2     = (const float*)d_in[6];
    const float* b2     = (const float*)d_in[7];
    float* out = (float*)d_out;

    cudaFuncSetAttribute(gemm_kernel, cudaFuncAttributeMaxDynamicSharedMemorySize, SMEM_GEMM);

    conv_kernel<<<3072, 256>>>(t_feat, W_proj, f_feat);
    dim3 grid(16, 4, 32);   // (btile, jt, kh*16 + cgroup) = 2048 CTAs, 2/SM
    gemm_kernel<<<grid, 256, SMEM_GEMM>>>();
    mlp_kernel<<<64, 32>>>(b_proj, W1, b1, W2, b2, out);
}

// round 16
// speedup vs baseline: 1.5699x; 1.0254x over previous
#include <cuda_runtime.h>
#include <cuda_fp16.h>
#include <cstdint>
#include <cstddef>

// ============================================================================
// proj[b,c] = sum_{i,j} t[b,i] * W[c, i*512+j] * f[b,j]   (B=2048, F=512, C=64)
// out = relu(relu(proj + bp) @ W1^T + b1) @ W2^T + b2
//
// fp16 mma.sync.m16n8k16. R16: same proven gemm core as R15 (64x32 warp tiles,
// 256thr / 2 CTAs/SM, K-split CTAs, B direct-LDG static ring-2). Changes:
//  - conv split into convW/convT/convF so GEMM is the 4th launch (ncu
//    empirically captures launch #4 -> gemm profile next round).
//  - parallel slice-reduce kernel + slim MLP (was ~8-10us, now ~6us total).
// ============================================================================

// g_T [bt256(8)][kc16(32)][mt(16)][lane(32)][4 u32]     (2 MB)
// g_W [c(64)][jt(4)][kc16(32)][nt(16)][lane(32)][2 u32] (33.5 MB)
__device__ uint32_t g_T[8 * 32 * 16 * 32 * 4];
__device__ uint32_t g_W[64 * 4 * 32 * 16 * 32 * 2];
__device__ __half   g_F[2048 * 512];                     // f in fp16 (2 MB)
__device__ float    g_partial[32 * 2048 * 64];           // 16 MB
__device__ float    g_proj[2048 * 64];                   // 0.5 MB

// ---------------- helpers ----------------
__device__ __forceinline__ uint32_t packh2(float lo, float hi) {
    __half2 h = __floats2half2_rn(lo, hi);
    return *(uint32_t*)&h;
}
__device__ __forceinline__ void cp16(uint32_t dst_smem, const void* src) {
    asm volatile("cp.async.cg.shared.global [%0], [%1], 16;" :: "r"(dst_smem), "l"(src));
}
__device__ __forceinline__ void cp_commit() {
    asm volatile("cp.async.commit_group;" ::: "memory");
}
__device__ __forceinline__ void mma_f16(float* d, const uint32_t* a, const uint32_t* b) {
    asm volatile(
        "mma.sync.aligned.m16n8k16.row.col.f32.f16.f16.f32 "
        "{%0,%1,%2,%3},{%4,%5,%6,%7},{%8,%9},{%0,%1,%2,%3};"
        : "+f"(d[0]), "+f"(d[1]), "+f"(d[2]), "+f"(d[3])
        : "r"(a[0]), "r"(a[1]), "r"(a[2]), "r"(a[3]), "r"(b[0]), "r"(b[1]));
}

// ---------------- convW: W -> fragment-order fp16 (smem transpose) ----------------
__global__ void convW_kernel(const float* __restrict__ W) {
    __shared__ float ws[64 * 132];
    int b = blockIdx.x;
    int c = b >> 5, jt = (b >> 3) & 3, ktile = b & 7;
    int tid = threadIdx.x, lane = tid & 31, warp = tid >> 5;

    const float* src = W + (size_t)c * 262144 + (size_t)(ktile * 64) * 512 + jt * 128;
#pragma unroll
    for (int r = 0; r < 8; r++) {
        int k = r * 8 + warp;
        float4 v = *(const float4*)&src[(size_t)k * 512 + lane * 4];
        float* d = &ws[k * 132 + lane * 4];
        d[0] = v.x; d[1] = v.y; d[2] = v.z; d[3] = v.w;
    }
    __syncthreads();

#pragma unroll
    for (int i = 0; i < 8; i++) {
        int p = warp * 8 + i;
        int q = p >> 4, nt = p & 15;
        int k0 = q * 16 + (lane & 3) * 2;
        int n  = nt * 8 + (lane >> 2);
        uint32_t v0 = packh2(ws[k0 * 132 + n],       ws[(k0 + 1) * 132 + n]);
        uint32_t v1 = packh2(ws[(k0 + 8) * 132 + n], ws[(k0 + 9) * 132 + n]);
        size_t base = ((size_t)((c * 4 + jt) * 32 + ktile * 4 + q) * 16 + nt) * 64 + lane * 2;
        *(uint2*)&g_W[base] = make_uint2(v0, v1);
    }
}

// ---------------- convT: t -> A fragments fp16 ----------------
__global__ void convT_kernel(const float* __restrict__ t) {
    int gid = blockIdx.x * 256 + threadIdx.x;   // 131072
    int lane  = gid & 31;
    int mt    = (gid >> 5) & 15;
    int kc    = (gid >> 9) & 31;
    int btile = gid >> 14;
    int row = btile * 256 + mt * 16 + (lane >> 2);
    int k0  = kc * 16 + (lane & 3) * 2;
    float2 p00 = *(const float2*)&t[(size_t)row * 512 + k0];
    float2 p10 = *(const float2*)&t[(size_t)(row + 8) * 512 + k0];
    float2 p01 = *(const float2*)&t[(size_t)row * 512 + k0 + 8];
    float2 p11 = *(const float2*)&t[(size_t)(row + 8) * 512 + k0 + 8];
    *(uint4*)&g_T[(size_t)gid * 4] =
        make_uint4(packh2(p00.x, p00.y), packh2(p10.x, p10.y),
                   packh2(p01.x, p01.y), packh2(p11.x, p11.y));
}

// ---------------- convF: f fp32 -> fp16 ----------------
__global__ void convF_kernel(const float* __restrict__ f) {
    int gid = blockIdx.x * 256 + threadIdx.x;   // 131072
    size_t i8 = (size_t)gid * 8;
    float4 a = *(const float4*)&f[i8];
    float4 b = *(const float4*)&f[i8 + 4];
    *(uint4*)&g_F[i8] = make_uint4(packh2(a.x, a.y), packh2(a.z, a.w),
                                   packh2(b.x, b.y), packh2(b.z, b.w));
}

// ---------------- GEMM + f-dot epilogue (R15 core, unchanged) ----------------
static constexpr uint32_t SMEM_AOFF = 65536;
static constexpr uint32_t SMEM_GEMM = 65536 + 128 * 136 * 2;   // 100352

__global__ __launch_bounds__(256, 2) void gemm_kernel() {
    extern __shared__ __align__(16) unsigned char smem_dyn[];
    uint32_t* smem = (uint32_t*)smem_dyn;
    int tid = threadIdx.x;
    int lane = tid & 31, warp = tid >> 5;
    int mw = warp & 1, nw = warp >> 1;
    int btile = blockIdx.x, jt = blockIdx.y;
    int cg = blockIdx.z & 15, kh = blockIdx.z >> 4;
    int c0 = cg * 4;

    const char* gA = (const char*)g_T + (size_t)(btile >> 1) * 262144
                   + (btile & 1) * 4096 + (size_t)kh * 16 * 8192;
    uint32_t sbase = (uint32_t)__cvta_generic_to_shared(smem);

#pragma unroll
    for (int g = 0; g < 4; g++) {
#pragma unroll
        for (int i = 0; i < 4; i++) {
            int slab = g * 4 + i;
            cp16(sbase + slab * 4096 + tid * 16, gA + (size_t)slab * 8192 + tid * 16);
        }
        cp_commit();
    }
#pragma unroll
    for (int r = 0; r < 8; r++) {
        int i = r * 256 + tid;
        int row = i >> 4, c16 = i & 15;
        const __half* fsrc = g_F + ((size_t)(btile * 128 + row) * 512 + jt * 128 + c16 * 8);
        cp16(sbase + SMEM_AOFF + row * 272 + c16 * 16, fsrc);
    }
    cp_commit();

    float acc[4][4][4];
#pragma unroll
    for (int mt = 0; mt < 4; mt++)
#pragma unroll
        for (int nt = 0; nt < 4; nt++)
#pragma unroll
            for (int q = 0; q < 4; q++) acc[mt][nt][q] = 0.f;

    const uint2* __restrict__ gB = (const uint2*)g_W;
    const size_t Bbase = ((size_t)(c0 * 4 + jt) * 32 + kh * 16) * 512 + nw * 128 + lane;
    uint2 bA[4], bB[4];
#pragma unroll
    for (int nt = 0; nt < 4; nt++) bA[nt] = gB[Bbase + nt * 32];
#pragma unroll
    for (int nt = 0; nt < 4; nt++) bB[nt] = gB[Bbase + 512 + nt * 32];

    const uint32_t* sA = smem;
    const __half2* fs = (const __half2*)(smem_dyn + SMEM_AOFF);

#pragma unroll 1
    for (int ci = 0; ci < 4; ci++) {
        size_t Bcur = Bbase + (size_t)ci * 65536;
        size_t Bnext = (ci < 3) ? Bcur + 65536 : Bcur;
#pragma unroll
        for (int kc2 = 0; kc2 < 8; kc2++) {
            const int kcA = kc2 * 2, kcB = kc2 * 2 + 1;
            if (ci == 0 && (kcA & 3) == 0) {
                switch (kcA >> 2) {
                    case 0: asm volatile("cp.async.wait_group 4;" ::: "memory"); break;
                    case 1: asm volatile("cp.async.wait_group 3;" ::: "memory"); break;
                    case 2: asm volatile("cp.async.wait_group 2;" ::: "memory"); break;
                    default: asm volatile("cp.async.wait_group 1;" ::: "memory"); break;
                }
                __syncthreads();
            }
            {
                const uint32_t* pA = sA + (size_t)kcA * 1024;
#pragma unroll
                for (int mt = 0; mt < 4; mt++) {
                    uint4 aa = *(const uint4*)&pA[((mw * 4 + mt) * 32 + lane) * 4];
                    uint32_t afr[4] = {aa.x, aa.y, aa.z, aa.w};
#pragma unroll
                    for (int nt = 0; nt < 4; nt++)
                        mma_f16(acc[mt][nt], afr, (const uint32_t*)&bA[nt]);
                }
                size_t pi = (kcA + 2 < 16) ? Bcur + (size_t)(kcA + 2) * 512
                                           : Bnext + (size_t)(kcA - 14) * 512;
#pragma unroll
                for (int nt = 0; nt < 4; nt++) bA[nt] = gB[pi + nt * 32];
            }
            {
                const uint32_t* pA = sA + (size_t)kcB * 1024;
#pragma unroll
                for (int mt = 0; mt < 4; mt++) {
                    uint4 aa = *(const uint4*)&pA[((mw * 4 + mt) * 32 + lane) * 4];
                    uint32_t afr[4] = {aa.x, aa.y, aa.z, aa.w};
#pragma unroll
                    for (int nt = 0; nt < 4; nt++)
                        mma_f16(acc[mt][nt], afr, (const uint32_t*)&bB[nt]);
                }
                size_t pi = (kcB + 2 < 16) ? Bcur + (size_t)(kcB + 2) * 512
                                           : Bnext + (size_t)(kcB - 14) * 512;
#pragma unroll
                for (int nt = 0; nt < 4; nt++) bB[nt] = gB[pi + nt * 32];
            }
        }

        if (ci == 0) {
            asm volatile("cp.async.wait_group 0;" ::: "memory");
            __syncthreads();
        }
        int c = c0 + ci;
        int slice = (jt * 4 + nw) * 2 + kh;
#pragma unroll
        for (int mt = 0; mt < 4; mt++) {
#pragma unroll
            for (int h = 0; h < 2; h++) {
                int fl = mw * 64 + mt * 16 + (lane >> 2) + 8 * h;
                float sum = 0.f;
#pragma unroll
                for (int nt = 0; nt < 4; nt++) {
                    __half2 hv = fs[fl * 68 + nw * 16 + nt * 4 + (lane & 3)];
                    float2 fv = __half22float2(hv);
                    sum = fmaf(acc[mt][nt][h * 2], fv.x, sum);
                    sum = fmaf(acc[mt][nt][h * 2 + 1], fv.y, sum);
                }
                sum += __shfl_xor_sync(0xffffffffu, sum, 1);
                sum += __shfl_xor_sync(0xffffffffu, sum, 2);
                if ((lane & 3) == 0) {
                    int bb = btile * 128 + fl;
                    g_partial[(size_t)slice * 131072 + (size_t)bb * 64 + c] = sum;
                }
            }
        }
#pragma unroll
        for (int mt = 0; mt < 4; mt++)
#pragma unroll
            for (int nt = 0; nt < 4; nt++)
#pragma unroll
                for (int q = 0; q < 4; q++) acc[mt][nt][q] = 0.f;
    }
}

// ---------------- reduce: 32 slices -> proj (parallel) ----------------
__global__ void reduce_kernel() {
    int gid = blockIdx.x * 256 + threadIdx.x;   // 32768 = 2048 b x 16 c-quads
    const float4* src = (const float4*)g_partial;
    float4 v = src[gid];
#pragma unroll
    for (int s = 1; s < 32; s++) {
        float4 p = src[(size_t)s * 32768 + gid];
        v.x += p.x; v.y += p.y; v.z += p.z; v.w += p.w;
    }
    ((float4*)g_proj)[gid] = v;
}

// ---------------- MLP: bias + relu + 64->32->1 ----------------
__global__ void mlp_kernel(const float* __restrict__ b_proj, const float* __restrict__ W1,
                           const float* __restrict__ b1, const float* __restrict__ W2,
                           const float* __restrict__ b2, float* __restrict__ out) {
    __shared__ float sW1[2048], sb1[32], sW2[32], sbp[64];
    int tid = threadIdx.x;
    for (int i = tid; i < 2048; i += 32) sW1[i] = W1[i];
    if (tid < 32) { sb1[tid] = b1[tid]; sW2[tid] = W2[tid]; }
    for (int i = tid; i < 64; i += 32) sbp[i] = b_proj[i];
    __syncthreads();

    int b = blockIdx.x * 32 + tid;
    float h[64];
#pragma unroll
    for (int cg = 0; cg < 16; cg++) {
        float4 v = *(const float4*)&g_proj[(size_t)b * 64 + cg * 4];
        h[cg * 4 + 0] = fmaxf(v.x + sbp[cg * 4 + 0], 0.f);
        h[cg * 4 + 1] = fmaxf(v.y + sbp[cg * 4 + 1], 0.f);
        h[cg * 4 + 2] = fmaxf(v.z + sbp[cg * 4 + 2], 0.f);
        h[cg * 4 + 3] = fmaxf(v.w + sbp[cg * 4 + 3], 0.f);
    }
    float logit = b2[0];
#pragma unroll
    for (int k = 0; k < 32; k++) {
        float a = sb1[k];
#pragma unroll
        for (int cc = 0; cc < 64; cc++)
            a = fmaf(h[cc], sW1[k * 64 + cc], a);
        logit = fmaf(fmaxf(a, 0.f), sW2[k], logit);
    }
    out[b] = logit;
}

// ---------------- launcher ----------------
extern "C" void kernel_launch(void* const* d_in, const int* in_sizes, int n_in,
                              void* d_out, int out_size) {
    const float* t_feat = (const float*)d_in[0];
    const float* f_feat = (const float*)d_in[1];
    const float* W_proj = (const float*)d_in[2];
    const float* b_proj = (const float*)d_in[3];
    const float* W1     = (const float*)d_in[4];
    const float* b1     = (const float*)d_in[5];
    const float* W2     = (const float*)d_in[6];
    const float* b2     = (const float*)d_in[7];
    float* out = (float*)d_out;

    cudaFuncSetAttribute(gemm_kernel, cudaFuncAttributeMaxDynamicSharedMemorySize, SMEM_GEMM);

    convW_kernel<<<2048, 256>>>(W_proj);       // launch 1
    convT_kernel<<<512, 256>>>(t_feat);        // launch 2
    convF_kernel<<<512, 256>>>(f_feat);        // launch 3
    dim3 grid(16, 4, 32);
    gemm_kernel<<<grid, 256, SMEM_GEMM>>>();   // launch 4  <- ncu captures this
    reduce_kernel<<<128, 256>>>();             // launch 5
    mlp_kernel<<<64, 32>>>(b_proj, W1, b1, W2, b2, out);   // launch 6
}

// round 17
// speedup vs baseline: 1.5727x; 1.0018x over previous
#include <cuda_runtime.h>
#include <cuda_fp16.h>
#include <cstdint>
#include <cstddef>

// ============================================================================
// proj[b,c] = sum_{i,j} t[b,i] * W[c, i*512+j] * f[b,j]   (B=2048, F=512, C=64)
// out = relu(relu(proj + bp) @ W1^T + b1) @ W2^T + b2
//
// fp16 mma.sync.m16n8k16. R17: identical shell to R16 (64x32 warp tiles,
// 256 thr / 2 CTAs/SM, K-split CTAs, B direct-LDG static ring-2, 6 launches
// with gemm at #4 for ncu capture). ONE change: all four A fragments loaded
// upfront per k-step (a0..a3) before the 16-mma burst -> one exposed LDS
// latency per step instead of four. R16 profile: tensor busy 113us (= HMMA
// floor), 58us exposure; this targets that exposure.
// ============================================================================

// g_T [bt256(8)][kc16(32)][mt(16)][lane(32)][4 u32]     (2 MB)
// g_W [c(64)][jt(4)][kc16(32)][nt(16)][lane(32)][2 u32] (33.5 MB)
__device__ uint32_t g_T[8 * 32 * 16 * 32 * 4];
__device__ uint32_t g_W[64 * 4 * 32 * 16 * 32 * 2];
__device__ __half   g_F[2048 * 512];                     // f in fp16 (2 MB)
__device__ float    g_partial[32 * 2048 * 64];           // 16 MB
__device__ float    g_proj[2048 * 64];                   // 0.5 MB

// ---------------- helpers ----------------
__device__ __forceinline__ uint32_t packh2(float lo, float hi) {
    __half2 h = __floats2half2_rn(lo, hi);
    return *(uint32_t*)&h;
}
__device__ __forceinline__ void cp16(uint32_t dst_smem, const void* src) {
    asm volatile("cp.async.cg.shared.global [%0], [%1], 16;" :: "r"(dst_smem), "l"(src));
}
__device__ __forceinline__ void cp_commit() {
    asm volatile("cp.async.commit_group;" ::: "memory");
}
__device__ __forceinline__ void mma_f16(float* d, const uint32_t* a, const uint32_t* b) {
    asm volatile(
        "mma.sync.aligned.m16n8k16.row.col.f32.f16.f16.f32 "
        "{%0,%1,%2,%3},{%4,%5,%6,%7},{%8,%9},{%0,%1,%2,%3};"
        : "+f"(d[0]), "+f"(d[1]), "+f"(d[2]), "+f"(d[3])
        : "r"(a[0]), "r"(a[1]), "r"(a[2]), "r"(a[3]), "r"(b[0]), "r"(b[1]));
}

// ---------------- convW: W -> fragment-order fp16 (smem transpose) ----------------
__global__ void convW_kernel(const float* __restrict__ W) {
    __shared__ float ws[64 * 132];
    int b = blockIdx.x;
    int c = b >> 5, jt = (b >> 3) & 3, ktile = b & 7;
    int tid = threadIdx.x, lane = tid & 31, warp = tid >> 5;

    const float* src = W + (size_t)c * 262144 + (size_t)(ktile * 64) * 512 + jt * 128;
#pragma unroll
    for (int r = 0; r < 8; r++) {
        int k = r * 8 + warp;
        float4 v = *(const float4*)&src[(size_t)k * 512 + lane * 4];
        float* d = &ws[k * 132 + lane * 4];
        d[0] = v.x; d[1] = v.y; d[2] = v.z; d[3] = v.w;
    }
    __syncthreads();

#pragma unroll
    for (int i = 0; i < 8; i++) {
        int p = warp * 8 + i;
        int q = p >> 4, nt = p & 15;
        int k0 = q * 16 + (lane & 3) * 2;
        int n  = nt * 8 + (lane >> 2);
        uint32_t v0 = packh2(ws[k0 * 132 + n],       ws[(k0 + 1) * 132 + n]);
        uint32_t v1 = packh2(ws[(k0 + 8) * 132 + n], ws[(k0 + 9) * 132 + n]);
        size_t base = ((size_t)((c * 4 + jt) * 32 + ktile * 4 + q) * 16 + nt) * 64 + lane * 2;
        *(uint2*)&g_W[base] = make_uint2(v0, v1);
    }
}

// ---------------- convT: t -> A fragments fp16 ----------------
__global__ void convT_kernel(const float* __restrict__ t) {
    int gid = blockIdx.x * 256 + threadIdx.x;   // 131072
    int lane  = gid & 31;
    int mt    = (gid >> 5) & 15;
    int kc    = (gid >> 9) & 31;
    int btile = gid >> 14;
    int row = btile * 256 + mt * 16 + (lane >> 2);
    int k0  = kc * 16 + (lane & 3) * 2;
    float2 p00 = *(const float2*)&t[(size_t)row * 512 + k0];
    float2 p10 = *(const float2*)&t[(size_t)(row + 8) * 512 + k0];
    float2 p01 = *(const float2*)&t[(size_t)row * 512 + k0 + 8];
    float2 p11 = *(const float2*)&t[(size_t)(row + 8) * 512 + k0 + 8];
    *(uint4*)&g_T[(size_t)gid * 4] =
        make_uint4(packh2(p00.x, p00.y), packh2(p10.x, p10.y),
                   packh2(p01.x, p01.y), packh2(p11.x, p11.y));
}

// ---------------- convF: f fp32 -> fp16 ----------------
__global__ void convF_kernel(const float* __restrict__ f) {
    int gid = blockIdx.x * 256 + threadIdx.x;   // 131072
    size_t i8 = (size_t)gid * 8;
    float4 a = *(const float4*)&f[i8];
    float4 b = *(const float4*)&f[i8 + 4];
    *(uint4*)&g_F[i8] = make_uint4(packh2(a.x, a.y), packh2(a.z, a.w),
                                   packh2(b.x, b.y), packh2(b.z, b.w));
}

// ---------------- GEMM + f-dot epilogue ----------------
static constexpr uint32_t SMEM_AOFF = 65536;
static constexpr uint32_t SMEM_GEMM = 65536 + 128 * 136 * 2;   // 100352

__global__ __launch_bounds__(256, 2) void gemm_kernel() {
    extern __shared__ __align__(16) unsigned char smem_dyn[];
    uint32_t* smem = (uint32_t*)smem_dyn;
    int tid = threadIdx.x;
    int lane = tid & 31, warp = tid >> 5;
    int mw = warp & 1, nw = warp >> 1;
    int btile = blockIdx.x, jt = blockIdx.y;
    int cg = blockIdx.z & 15, kh = blockIdx.z >> 4;
    int c0 = cg * 4;

    const char* gA = (const char*)g_T + (size_t)(btile >> 1) * 262144
                   + (btile & 1) * 4096 + (size_t)kh * 16 * 8192;
    uint32_t sbase = (uint32_t)__cvta_generic_to_shared(smem);

#pragma unroll
    for (int g = 0; g < 4; g++) {
#pragma unroll
        for (int i = 0; i < 4; i++) {
            int slab = g * 4 + i;
            cp16(sbase + slab * 4096 + tid * 16, gA + (size_t)slab * 8192 + tid * 16);
        }
        cp_commit();
    }
#pragma unroll
    for (int r = 0; r < 8; r++) {
        int i = r * 256 + tid;
        int row = i >> 4, c16 = i & 15;
        const __half* fsrc = g_F + ((size_t)(btile * 128 + row) * 512 + jt * 128 + c16 * 8);
        cp16(sbase + SMEM_AOFF + row * 272 + c16 * 16, fsrc);
    }
    cp_commit();

    float acc[4][4][4];
#pragma unroll
    for (int mt = 0; mt < 4; mt++)
#pragma unroll
        for (int nt = 0; nt < 4; nt++)
#pragma unroll
            for (int q = 0; q < 4; q++) acc[mt][nt][q] = 0.f;

    const uint2* __restrict__ gB = (const uint2*)g_W;
    const size_t Bbase = ((size_t)(c0 * 4 + jt) * 32 + kh * 16) * 512 + nw * 128 + lane;
    uint2 bA[4], bB[4];
#pragma unroll
    for (int nt = 0; nt < 4; nt++) bA[nt] = gB[Bbase + nt * 32];
#pragma unroll
    for (int nt = 0; nt < 4; nt++) bB[nt] = gB[Bbase + 512 + nt * 32];

    const uint32_t* sA = smem;
    const __half2* fs = (const __half2*)(smem_dyn + SMEM_AOFF);

#pragma unroll 1
    for (int ci = 0; ci < 4; ci++) {
        size_t Bcur = Bbase + (size_t)ci * 65536;
        size_t Bnext = (ci < 3) ? Bcur + 65536 : Bcur;
#pragma unroll
        for (int kc2 = 0; kc2 < 8; kc2++) {
            const int kcA = kc2 * 2, kcB = kc2 * 2 + 1;
            if (ci == 0 && (kcA & 3) == 0) {
                switch (kcA >> 2) {
                    case 0: asm volatile("cp.async.wait_group 4;" ::: "memory"); break;
                    case 1: asm volatile("cp.async.wait_group 3;" ::: "memory"); break;
                    case 2: asm volatile("cp.async.wait_group 2;" ::: "memory"); break;
                    default: asm volatile("cp.async.wait_group 1;" ::: "memory"); break;
                }
                __syncthreads();
            }
            // ---- step kcA: all 4 A fragments upfront, 16-mma burst, then B reload ----
            {
                const uint32_t* pA = sA + (size_t)kcA * 1024;
                uint4 a0 = *(const uint4*)&pA[((mw * 4 + 0) * 32 + lane) * 4];
                uint4 a1 = *(const uint4*)&pA[((mw * 4 + 1) * 32 + lane) * 4];
                uint4 a2 = *(const uint4*)&pA[((mw * 4 + 2) * 32 + lane) * 4];
                uint4 a3 = *(const uint4*)&pA[((mw * 4 + 3) * 32 + lane) * 4];
#pragma unroll
                for (int nt = 0; nt < 4; nt++) mma_f16(acc[0][nt], (const uint32_t*)&a0, (const uint32_t*)&bA[nt]);
#pragma unroll
                for (int nt = 0; nt < 4; nt++) mma_f16(acc[1][nt], (const uint32_t*)&a1, (const uint32_t*)&bA[nt]);
#pragma unroll
                for (int nt = 0; nt < 4; nt++) mma_f16(acc[2][nt], (const uint32_t*)&a2, (const uint32_t*)&bA[nt]);
#pragma unroll
                for (int nt = 0; nt < 4; nt++) mma_f16(acc[3][nt], (const uint32_t*)&a3, (const uint32_t*)&bA[nt]);
                size_t pi = (kcA + 2 < 16) ? Bcur + (size_t)(kcA + 2) * 512
                                           : Bnext + (size_t)(kcA - 14) * 512;
#pragma unroll
                for (int nt = 0; nt < 4; nt++) bA[nt] = gB[pi + nt * 32];
            }
            // ---- step kcB ----
            {
                const uint32_t* pA = sA + (size_t)kcB * 1024;
                uint4 a0 = *(const uint4*)&pA[((mw * 4 + 0) * 32 + lane) * 4];
                uint4 a1 = *(const uint4*)&pA[((mw * 4 + 1) * 32 + lane) * 4];
                uint4 a2 = *(const uint4*)&pA[((mw * 4 + 2) * 32 + lane) * 4];
                uint4 a3 = *(const uint4*)&pA[((mw * 4 + 3) * 32 + lane) * 4];
#pragma unroll
                for (int nt = 0; nt < 4; nt++) mma_f16(acc[0][nt], (const uint32_t*)&a0, (const uint32_t*)&bB[nt]);
#pragma unroll
                for (int nt = 0; nt < 4; nt++) mma_f16(acc[1][nt], (const uint32_t*)&a1, (const uint32_t*)&bB[nt]);
#pragma unroll
                for (int nt = 0; nt < 4; nt++) mma_f16(acc[2][nt], (const uint32_t*)&a2, (const uint32_t*)&bB[nt]);
#pragma unroll
                for (int nt = 0; nt < 4; nt++) mma_f16(acc[3][nt], (const uint32_t*)&a3, (const uint32_t*)&bB[nt]);
                size_t pi = (kcB + 2 < 16) ? Bcur + (size_t)(kcB + 2) * 512
                                           : Bnext + (size_t)(kcB - 14) * 512;
#pragma unroll
                for (int nt = 0; nt < 4; nt++) bB[nt] = gB[pi + nt * 32];
            }
        }

        if (ci == 0) {
            asm volatile("cp.async.wait_group 0;" ::: "memory");
            __syncthreads();
        }
        int c = c0 + ci;
        int slice = (jt * 4 + nw) * 2 + kh;
#pragma unroll
        for (int mt = 0; mt < 4; mt++) {
#pragma unroll
            for (int h = 0; h < 2; h++) {
                int fl = mw * 64 + mt * 16 + (lane >> 2) + 8 * h;
                float sum = 0.f;
#pragma unroll
                for (int nt = 0; nt < 4; nt++) {
                    __half2 hv = fs[fl * 68 + nw * 16 + nt * 4 + (lane & 3)];
                    float2 fv = __half22float2(hv);
                    sum = fmaf(acc[mt][nt][h * 2], fv.x, sum);
                    sum = fmaf(acc[mt][nt][h * 2 + 1], fv.y, sum);
                }
                sum += __shfl_xor_sync(0xffffffffu, sum, 1);
                sum += __shfl_xor_sync(0xffffffffu, sum, 2);
                if ((lane & 3) == 0) {
                    int bb = btile * 128 + fl;
                    g_partial[(size_t)slice * 131072 + (size_t)bb * 64 + c] = sum;
                }
            }
        }
#pragma unroll
        for (int mt = 0; mt < 4; mt++)
#pragma unroll
            for (int nt = 0; nt < 4; nt++)
#pragma unroll
                for (int q = 0; q < 4; q++) acc[mt][nt][q] = 0.f;
    }
}

// ---------------- reduce: 32 slices -> proj (parallel) ----------------
__global__ void reduce_kernel() {
    int gid = blockIdx.x * 256 + threadIdx.x;   // 32768 = 2048 b x 16 c-quads
    const float4* src = (const float4*)g_partial;
    float4 v = src[gid];
#pragma unroll
    for (int s = 1; s < 32; s++) {
        float4 p = src[(size_t)s * 32768 + gid];
        v.x += p.x; v.y += p.y; v.z += p.z; v.w += p.w;
    }
    ((float4*)g_proj)[gid] = v;
}

// ---------------- MLP: bias + relu + 64->32->1 ----------------
__global__ void mlp_kernel(const float* __restrict__ b_proj, const float* __restrict__ W1,
                           const float* __restrict__ b1, const float* __restrict__ W2,
                           const float* __restrict__ b2, float* __restrict__ out) {
    __shared__ float sW1[2048], sb1[32], sW2[32], sbp[64];
    int tid = threadIdx.x;
    for (int i = tid; i < 2048; i += 32) sW1[i] = W1[i];
    if (tid < 32) { sb1[tid] = b1[tid]; sW2[tid] = W2[tid]; }
    for (int i = tid; i < 64; i += 32) sbp[i] = b_proj[i];
    __syncthreads();

    int b = blockIdx.x * 32 + tid;
    float h[64];
#pragma unroll
    for (int cg = 0; cg < 16; cg++) {
        float4 v = *(const float4*)&g_proj[(size_t)b * 64 + cg * 4];
        h[cg * 4 + 0] = fmaxf(v.x + sbp[cg * 4 + 0], 0.f);
        h[cg * 4 + 1] = fmaxf(v.y + sbp[cg * 4 + 1], 0.f);
        h[cg * 4 + 2] = fmaxf(v.z + sbp[cg * 4 + 2], 0.f);
        h[cg * 4 + 3] = fmaxf(v.w + sbp[cg * 4 + 3], 0.f);
    }
    float logit = b2[0];
#pragma unroll
    for (int k = 0; k < 32; k++) {
        float a = sb1[k];
#pragma unroll
        for (int cc = 0; cc < 64; cc++)
            a = fmaf(h[cc], sW1[k * 64 + cc], a);
        logit = fmaf(fmaxf(a, 0.f), sW2[k], logit);
    }
    out[b] = logit;
}

// ---------------- launcher ----------------
extern "C" void kernel_launch(void* const* d_in, const int* in_sizes, int n_in,
                              void* d_out, int out_size) {
    const float* t_feat = (const float*)d_in[0];
    const float* f_feat = (const float*)d_in[1];
    const float* W_proj = (const float*)d_in[2];
    const float* b_proj = (const float*)d_in[3];
    const float* W1     = (const float*)d_in[4];
    const float* b1     = (const float*)d_in[5];
    const float* W2     = (const float*)d_in[6];
    const float* b2     = (const float*)d_in[7];
    float* out = (float*)d_out;

    cudaFuncSetAttribute(gemm_kernel, cudaFuncAttributeMaxDynamicSharedMemorySize, SMEM_GEMM);

    convW_kernel<<<2048, 256>>>(W_proj);       // launch 1
    convT_kernel<<<512, 256>>>(t_feat);        // launch 2
    convF_kernel<<<512, 256>>>(f_feat);        // launch 3
    dim3 grid(16, 4, 32);
    gemm_kernel<<<grid, 256, SMEM_GEMM>>>();   // launch 4  <- ncu captures this
    reduce_kernel<<<128, 256>>>();             // launch 5
    mlp_kernel<<<64, 32>>>(b_proj, W1, b1, W2, b2, out);   // launch 6
}